// round 4
// baseline (speedup 1.0000x reference)
#include <cuda_runtime.h>
#include <math.h>

#define NTOK 2048
#define NHEAD 8
#define DK 512
#define CIN 256
#define HWSZ 64   // 8x8 spatial
#define OUTCH 64  // projection out channels

// ---------------- packed f32x2 helpers (Blackwell FFMA2) ----------------
__device__ __forceinline__ unsigned long long f32x2_pack2(float x) {
    unsigned long long r;
    asm("mov.b64 %0, {%1, %1};" : "=l"(r) : "f"(x));
    return r;
}
__device__ __forceinline__ void f32x2_fma(unsigned long long& d,
                                          unsigned long long a,
                                          unsigned long long b) {
    asm("fma.rn.f32x2 %0, %1, %2, %0;" : "+l"(d) : "l"(a), "l"(b));
}
__device__ __forceinline__ float2 f32x2_unpack(unsigned long long v) {
    float2 r;
    asm("mov.b64 {%0, %1}, %2;" : "=f"(r.x), "=f"(r.y) : "l"(v));
    return r;
}

// ---------------- device scratch (no cudaMalloc allowed) ----------------
__device__ float g_qh[(size_t)NHEAD * NTOK * DK];
__device__ float g_kh[(size_t)NHEAD * NTOK * DK];
__device__ float g_vh[(size_t)NHEAD * NTOK * DK];
__device__ float g_o [(size_t)NHEAD * NTOK * DK];
__device__ float g_attn_scratch[(size_t)NHEAD * NTOK * NTOK];

// =====================================================================
// Kernel 1: per-sample projection.  For sample n:
//   Y[o][hw] = sum_c W[o][c] * x[n][c][hw] + b[o]   (64x256 @ 256x64)
// stored as heads: dst[h][n][d], h = o>>3, d = (o&7)*64 + hw
// =====================================================================
__global__ __launch_bounds__(256) void proj_kernel(
    const float* __restrict__ x, const float* __restrict__ W,
    const float* __restrict__ b, float* __restrict__ dst)
{
    __shared__ float Xs[64][68];   // [c'][hw]  (row stride 272B, 16B aligned)
    __shared__ float Ws[64][68];   // [o][c']
    const int n = blockIdx.x;
    const int t = threadIdx.x;
    const int to  = (t >> 4) * 4;   // 4 output channels
    const int thw = (t & 15) * 4;   // 4 spatial cols

    const float* xn = x + (size_t)n * CIN * HWSZ;
    unsigned long long acc2[4][2];
    #pragma unroll
    for (int i = 0; i < 4; i++) { acc2[i][0] = 0ull; acc2[i][1] = 0ull; }

    for (int cc = 0; cc < CIN; cc += 64) {
        __syncthreads();
        #pragma unroll
        for (int i = 0; i < 16; i++) {
            int e = i * 256 + t;
            int r = e >> 6, c = e & 63;
            Xs[r][c] = xn[(size_t)cc * 64 + e];           // x[n][cc+r][c]
            Ws[r][c] = W[(size_t)r * CIN + cc + c];       // W[r][cc+c]
        }
        __syncthreads();
        #pragma unroll
        for (int c1 = 0; c1 < 64; c1++) {
            ulonglong2 bp = *(const ulonglong2*)&Xs[c1][thw];
            #pragma unroll
            for (int i = 0; i < 4; i++) {
                unsigned long long aa = f32x2_pack2(Ws[to + i][c1]);
                f32x2_fma(acc2[i][0], aa, bp.x);
                f32x2_fma(acc2[i][1], aa, bp.y);
            }
        }
    }

    #pragma unroll
    for (int i = 0; i < 4; i++) {
        int o = to + i;
        float bias = b[o];
        int h = o >> 3;
        int dbase = (o & 7) * 64;
        float* dp = dst + ((size_t)h * NTOK + n) * DK + dbase + thw;
        float2 p0 = f32x2_unpack(acc2[i][0]);
        float2 p1 = f32x2_unpack(acc2[i][1]);
        float4 outv = make_float4(p0.x + bias, p0.y + bias,
                                  p1.x + bias, p1.y + bias);
        *(float4*)dp = outv;
    }
}

// =====================================================================
// Kernel 2/4: 128x128 tiled SGEMM, double-buffered smem, FFMA2 inner.
//   B_NT=true : C[m][n] = alpha * sum_k A[m][k] * B[n][k]   (B row-major NxK)
//   B_NT=false: C[m][n] = alpha * sum_k A[m][k] * B[k][n]   (B row-major KxN)
// =====================================================================
template<bool B_NT>
__global__ __launch_bounds__(256) void gemm128x128(
    const float* __restrict__ A, const float* __restrict__ B, float* __restrict__ C,
    int K, int lda, int ldb, int ldc,
    long long sA, long long sB, long long sC, float alpha)
{
    __shared__ float As[2][8][128];
    __shared__ float Bs[2][8][128];

    const float* Ab = A + (long long)blockIdx.z * sA;
    const float* Bb = B + (long long)blockIdx.z * sB;
    float*       Cb = C + (long long)blockIdx.z * sC;

    const int m0 = blockIdx.y * 128;
    const int n0 = blockIdx.x * 128;
    const int t  = threadIdx.x;
    const int tx = t & 15, ty = t >> 4;

    const int arow = t >> 1;             // 0..127
    const int acol = (t & 1) * 4;        // 0 or 4
    const int brow = t >> 5;             // 0..7   (NN)
    const int bcol = (t & 31) * 4;       // 0..124 (NN)

    const float* Aptr = &Ab[(long long)(m0 + arow) * lda + acol];
    const float* Bptr = B_NT ? &Bb[(long long)(n0 + arow) * ldb + acol]
                             : &Bb[(long long)brow * ldb + n0 + bcol];
    const long long bstep = B_NT ? 8 : (long long)8 * ldb;

    unsigned long long acc2[8][4];
    #pragma unroll
    for (int i = 0; i < 8; i++)
        #pragma unroll
        for (int j = 0; j < 4; j++) acc2[i][j] = 0ull;

    const int niter = K >> 3;

    // ---- prologue: stage tile 0 ----
    {
        float4 av = *(const float4*)Aptr;
        float4 bv = *(const float4*)Bptr;
        As[0][acol + 0][arow] = av.x; As[0][acol + 1][arow] = av.y;
        As[0][acol + 2][arow] = av.z; As[0][acol + 3][arow] = av.w;
        if (B_NT) {
            Bs[0][acol + 0][arow] = bv.x; Bs[0][acol + 1][arow] = bv.y;
            Bs[0][acol + 2][arow] = bv.z; Bs[0][acol + 3][arow] = bv.w;
        } else {
            *(float4*)&Bs[0][brow][bcol] = bv;
        }
    }
    __syncthreads();

    for (int it = 0; it < niter; it++) {
        const int buf = it & 1;

        // prefetch next tile from global BEFORE compute (latency overlap)
        float4 nav, nbv;
        const bool have_next = (it + 1 < niter);
        if (have_next) {
            nav = *(const float4*)(Aptr + (long long)(it + 1) * 8);
            nbv = *(const float4*)(Bptr + (long long)(it + 1) * bstep);
        }

        #pragma unroll
        for (int kk = 0; kk < 8; kk++) {
            float4 a0 = *(const float4*)&As[buf][kk][ty * 4];
            float4 a1 = *(const float4*)&As[buf][kk][ty * 4 + 64];
            ulonglong2 bA = *(const ulonglong2*)&Bs[buf][kk][tx * 4];
            ulonglong2 bB = *(const ulonglong2*)&Bs[buf][kk][tx * 4 + 64];
            float a[8] = {a0.x, a0.y, a0.z, a0.w, a1.x, a1.y, a1.z, a1.w};
            #pragma unroll
            for (int i = 0; i < 8; i++) {
                unsigned long long aa = f32x2_pack2(a[i]);
                f32x2_fma(acc2[i][0], aa, bA.x);
                f32x2_fma(acc2[i][1], aa, bA.y);
                f32x2_fma(acc2[i][2], aa, bB.x);
                f32x2_fma(acc2[i][3], aa, bB.y);
            }
        }

        if (have_next) {
            const int nb = buf ^ 1;
            As[nb][acol + 0][arow] = nav.x; As[nb][acol + 1][arow] = nav.y;
            As[nb][acol + 2][arow] = nav.z; As[nb][acol + 3][arow] = nav.w;
            if (B_NT) {
                Bs[nb][acol + 0][arow] = nbv.x; Bs[nb][acol + 1][arow] = nbv.y;
                Bs[nb][acol + 2][arow] = nbv.z; Bs[nb][acol + 3][arow] = nbv.w;
            } else {
                *(float4*)&Bs[nb][brow][bcol] = nbv;
            }
            __syncthreads();
        }
    }

    #pragma unroll
    for (int i = 0; i < 8; i++) {
        int row = m0 + ty * 4 + (i & 3) + ((i & 4) ? 64 : 0);
        float2 p0 = f32x2_unpack(acc2[i][0]);
        float2 p1 = f32x2_unpack(acc2[i][1]);
        float2 p2 = f32x2_unpack(acc2[i][2]);
        float2 p3 = f32x2_unpack(acc2[i][3]);
        float4 o0 = make_float4(alpha * p0.x, alpha * p0.y,
                                alpha * p1.x, alpha * p1.y);
        float4 o1 = make_float4(alpha * p2.x, alpha * p2.y,
                                alpha * p3.x, alpha * p3.y);
        *(float4*)&Cb[(long long)row * ldc + n0 + tx * 4]      = o0;
        *(float4*)&Cb[(long long)row * ldc + n0 + 64 + tx * 4] = o1;
    }
}

// =====================================================================
// Kernel 3: in-place row softmax over 2048 columns (one block per row)
// =====================================================================
__global__ __launch_bounds__(256) void softmax_rows(float* __restrict__ attn)
{
    float4* p4 = (float4*)(attn + (long long)blockIdx.x * NTOK);
    const int t = threadIdx.x;
    __shared__ float red[8];

    float4 v0 = p4[t];
    float4 v1 = p4[t + 256];

    float m = fmaxf(fmaxf(fmaxf(v0.x, v0.y), fmaxf(v0.z, v0.w)),
                    fmaxf(fmaxf(v1.x, v1.y), fmaxf(v1.z, v1.w)));
    #pragma unroll
    for (int o = 16; o; o >>= 1) m = fmaxf(m, __shfl_xor_sync(0xffffffffu, m, o));
    if ((t & 31) == 0) red[t >> 5] = m;
    __syncthreads();
    if (t < 32) {
        float r = (t < 8) ? red[t] : -3.4e38f;
        #pragma unroll
        for (int o = 4; o; o >>= 1) r = fmaxf(r, __shfl_xor_sync(0xffffffffu, r, o));
        if (t == 0) red[0] = r;
    }
    __syncthreads();
    m = red[0];
    __syncthreads();

    v0.x = __expf(v0.x - m); v0.y = __expf(v0.y - m);
    v0.z = __expf(v0.z - m); v0.w = __expf(v0.w - m);
    v1.x = __expf(v1.x - m); v1.y = __expf(v1.y - m);
    v1.z = __expf(v1.z - m); v1.w = __expf(v1.w - m);

    float s = v0.x + v0.y + v0.z + v0.w + v1.x + v1.y + v1.z + v1.w;
    #pragma unroll
    for (int o = 16; o; o >>= 1) s += __shfl_xor_sync(0xffffffffu, s, o);
    if ((t & 31) == 0) red[t >> 5] = s;
    __syncthreads();
    if (t < 32) {
        float r = (t < 8) ? red[t] : 0.0f;
        #pragma unroll
        for (int o = 4; o; o >>= 1) r += __shfl_xor_sync(0xffffffffu, r, o);
        if (t == 0) red[0] = r;
    }
    __syncthreads();
    float inv = 1.0f / red[0];

    v0.x *= inv; v0.y *= inv; v0.z *= inv; v0.w *= inv;
    v1.x *= inv; v1.y *= inv; v1.z *= inv; v1.w *= inv;
    p4[t] = v0;
    p4[t + 256] = v1;
}

// =====================================================================
// Kernel 5: fc (1x1 conv) + residual + InstanceNorm, one block per sample.
//   y[c][hw] = sum_oc Wfc[c][oc]*att[oc][hw] + bfc[c] + q[n][c][hw]
//   out = (y - mean_hw) * rsqrt(var_hw + eps)
// att[oc][hw] = g_o[h=oc>>3][n][d=(oc&7)*64+hw]
// =====================================================================
#define K3_SMEM ((256 * 65 + 64 * 68 + 256 * 68) * 4)
__global__ __launch_bounds__(256) void fc_norm_kernel(
    const float* __restrict__ oatt, const float* __restrict__ Wfc,
    const float* __restrict__ bfc, const float* __restrict__ q,
    float* __restrict__ out)
{
    extern __shared__ float sm[];
    float* Wfs = sm;                 // 256 x 65
    float* att = Wfs + 256 * 65;     // 64 x 68  (base 66560B, 16B aligned)
    float* ys  = att + 64 * 68;      // 256 x 68

    const int n = blockIdx.x;
    const int t = threadIdx.x;

    #pragma unroll 4
    for (int i = 0; i < 64; i++) {
        int e = i * 256 + t;
        Wfs[(e >> 6) * 65 + (e & 63)] = Wfc[e];
        ys[(e >> 6) * 68 + (e & 63)] = q[(size_t)n * 16384 + e];
    }
    #pragma unroll
    for (int i = 0; i < 16; i++) {
        int e = i * 256 + t;
        int oc = e >> 6, hw = e & 63;
        att[oc * 68 + hw] =
            oatt[((size_t)(oc >> 3) * NTOK + n) * DK + (oc & 7) * 64 + hw];
    }
    __syncthreads();

    const int c = t;
    unsigned long long acc2[32];
    #pragma unroll
    for (int j = 0; j < 32; j++) acc2[j] = 0ull;

    for (int oc = 0; oc < 64; oc++) {
        unsigned long long aa = f32x2_pack2(Wfs[c * 65 + oc]);
        const ulonglong2* arow = (const ulonglong2*)&att[oc * 68];
        #pragma unroll
        for (int j = 0; j < 16; j++) {
            ulonglong2 v = arow[j];
            f32x2_fma(acc2[2 * j + 0], aa, v.x);
            f32x2_fma(acc2[2 * j + 1], aa, v.y);
        }
    }

    float bias = bfc[c];
    float4* yrow = (float4*)&ys[c * 68];
    float s = 0.f, s2 = 0.f;
    float4 accf[16];
    #pragma unroll
    for (int j = 0; j < 16; j++) {
        float2 p0 = f32x2_unpack(acc2[2 * j + 0]);
        float2 p1 = f32x2_unpack(acc2[2 * j + 1]);
        float4 r = yrow[j];
        float4 a;
        a.x = p0.x + bias + r.x; a.y = p0.y + bias + r.y;
        a.z = p1.x + bias + r.z; a.w = p1.y + bias + r.w;
        accf[j] = a;
        s  += a.x + a.y + a.z + a.w;
        s2 += a.x * a.x + a.y * a.y + a.z * a.z + a.w * a.w;
    }
    float mean = s * (1.0f / 64.0f);
    float var  = s2 * (1.0f / 64.0f) - mean * mean;
    float inv  = rsqrtf(var + 1e-5f);
    #pragma unroll
    for (int j = 0; j < 16; j++) {
        float4 a = accf[j];
        a.x = (a.x - mean) * inv; a.y = (a.y - mean) * inv;
        a.z = (a.z - mean) * inv; a.w = (a.w - mean) * inv;
        yrow[j] = a;
    }
    __syncthreads();
    #pragma unroll 4
    for (int i = 0; i < 64; i++) {
        int e = i * 256 + t;
        out[(size_t)n * 16384 + e] = ys[(e >> 6) * 68 + (e & 63)];
    }
}

// =====================================================================
extern "C" void kernel_launch(void* const* d_in, const int* in_sizes, int n_in,
                              void* d_out, int out_size)
{
    const float* q   = (const float*)d_in[0];
    const float* k   = (const float*)d_in[1];
    const float* v   = (const float*)d_in[2];
    const float* Wq  = (const float*)d_in[3];
    const float* bq  = (const float*)d_in[4];
    const float* Wk  = (const float*)d_in[5];
    const float* bk  = (const float*)d_in[6];
    const float* Wv  = (const float*)d_in[7];
    const float* bv  = (const float*)d_in[8];
    const float* Wfc = (const float*)d_in[9];
    const float* bfc = (const float*)d_in[10];
    float* out = (float*)d_out;

    float *p_qh, *p_kh, *p_vh, *p_o, *p_attn_scr;
    cudaGetSymbolAddress((void**)&p_qh, g_qh);
    cudaGetSymbolAddress((void**)&p_kh, g_kh);
    cudaGetSymbolAddress((void**)&p_vh, g_vh);
    cudaGetSymbolAddress((void**)&p_o,  g_o);
    cudaGetSymbolAddress((void**)&p_attn_scr, g_attn_scratch);

    const size_t OUT_ELEMS  = (size_t)NTOK * CIN * HWSZ;          // 33554432
    const size_t ATTN_ELEMS = (size_t)NHEAD * NTOK * NTOK;        // 33554432
    // attn goes into d_out if it's part of the output, else into scratch
    float* attn = ((size_t)out_size >= OUT_ELEMS + ATTN_ELEMS)
                      ? out + OUT_ELEMS : p_attn_scr;

    // 1) projections
    proj_kernel<<<NTOK, 256>>>(q, Wq, bq, p_qh);
    proj_kernel<<<NTOK, 256>>>(k, Wk, bk, p_kh);
    proj_kernel<<<NTOK, 256>>>(v, Wv, bv, p_vh);

    // 2) scores = (Q K^T) / sqrt(512)
    {
        dim3 grid(NTOK / 128, NTOK / 128, NHEAD);
        gemm128x128<true><<<grid, 256>>>(
            p_qh, p_kh, attn, DK, DK, DK, NTOK,
            (long long)NTOK * DK, (long long)NTOK * DK, (long long)NTOK * NTOK,
            0.04419417382415922f /* 1/sqrt(512) */);
    }

    // 3) softmax over keys, in place
    softmax_rows<<<NHEAD * NTOK, 256>>>(attn);

    // 4) O = P @ V
    {
        dim3 grid(DK / 128, NTOK / 128, NHEAD);
        gemm128x128<false><<<grid, 256>>>(
            attn, p_vh, p_o, NTOK, NTOK, DK, DK,
            (long long)NTOK * NTOK, (long long)NTOK * DK, (long long)NTOK * DK,
            1.0f);
    }

    // 5) fc + residual + instance norm
    cudaFuncSetAttribute(fc_norm_kernel,
                         cudaFuncAttributeMaxDynamicSharedMemorySize, K3_SMEM);
    fc_norm_kernel<<<NTOK, 256, K3_SMEM>>>(p_o, Wfc, bfc, q, out);
}

// round 9
// speedup vs baseline: 1.1544x; 1.1544x over previous
#include <cuda_runtime.h>
#include <math.h>
#include <stdint.h>

#define NTOK 2048
#define NHEAD 8
#define DK 512
#define CIN 256
#define HWSZ 64
#define ATTN_SCALE 0.04419417382415922f  // 1/sqrt(512)

// ---------------- device scratch (no cudaMalloc allowed) ----------------
#define HTD ((size_t)NHEAD * NTOK * DK)
__device__ float g_qhi[HTD];
__device__ float g_qlo[HTD];
__device__ float g_khi[HTD];
__device__ float g_klo[HTD];
__device__ float g_vhi[HTD];
__device__ float g_vlo[HTD];
__device__ float g_o  [HTD];
__device__ float g_attn_scratch[(size_t)NHEAD * NTOK * NTOK];

// ---------------- small helpers ----------------
__device__ __forceinline__ uint32_t tf32_of(float x) {
    uint32_t r;
    asm("cvt.rna.tf32.f32 %0, %1;" : "=r"(r) : "f"(x));
    return r;
}
__device__ __forceinline__ void cpa16(uint32_t saddr, const void* gptr) {
    asm volatile("cp.async.ca.shared.global [%0], [%1], 16;"
                 :: "r"(saddr), "l"(gptr));
}
__device__ __forceinline__ void cpa_commit() {
    asm volatile("cp.async.commit_group;");
}
__device__ __forceinline__ void cpa_wait0() {
    asm volatile("cp.async.wait_group 0;");
}
__device__ __forceinline__ void mma8(float* d, const uint32_t* a, const uint32_t* b) {
    asm volatile(
        "mma.sync.aligned.m16n8k8.row.col.f32.tf32.tf32.f32 "
        "{%0,%1,%2,%3}, {%4,%5,%6,%7}, {%8,%9}, {%0,%1,%2,%3};"
        : "+f"(d[0]), "+f"(d[1]), "+f"(d[2]), "+f"(d[3])
        : "r"(a[0]), "r"(a[1]), "r"(a[2]), "r"(a[3]),
          "r"(b[0]), "r"(b[1]));
}
__device__ __forceinline__ uint32_t fbits(float x) { return __float_as_uint(x); }

// =====================================================================
// Kernel 1: projection (scalar fp32) + tf32 hi/lo split epilogue
//   Y[o][hw] = sum_c W[o][c]*x[n][c][hw] + b[o]
// stored as heads: dst[h][n][d], h=o>>3, d=(o&7)*64+hw  (hi and lo bufs)
// =====================================================================
__global__ __launch_bounds__(256) void proj_kernel(
    const float* __restrict__ x, const float* __restrict__ W,
    const float* __restrict__ b,
    float* __restrict__ dhi, float* __restrict__ dlo)
{
    __shared__ float Xs[64][68];
    __shared__ float Ws[64][68];
    const int n = blockIdx.x;
    const int t = threadIdx.x;
    const int to  = (t >> 4) * 4;
    const int thw = (t & 15) * 4;

    const float* xn = x + (size_t)n * CIN * HWSZ;
    float acc[4][4] = {};

    for (int cc = 0; cc < CIN; cc += 64) {
        __syncthreads();
        #pragma unroll
        for (int i = 0; i < 16; i++) {
            int e = i * 256 + t;
            int r = e >> 6, c = e & 63;
            Xs[r][c] = xn[(size_t)cc * 64 + e];
            Ws[r][c] = W[(size_t)r * CIN + cc + c];
        }
        __syncthreads();
        #pragma unroll
        for (int c1 = 0; c1 < 64; c1++) {
            float a0 = Ws[to + 0][c1];
            float a1 = Ws[to + 1][c1];
            float a2 = Ws[to + 2][c1];
            float a3 = Ws[to + 3][c1];
            float4 bv = *(const float4*)&Xs[c1][thw];
            acc[0][0] += a0 * bv.x; acc[0][1] += a0 * bv.y; acc[0][2] += a0 * bv.z; acc[0][3] += a0 * bv.w;
            acc[1][0] += a1 * bv.x; acc[1][1] += a1 * bv.y; acc[1][2] += a1 * bv.z; acc[1][3] += a1 * bv.w;
            acc[2][0] += a2 * bv.x; acc[2][1] += a2 * bv.y; acc[2][2] += a2 * bv.z; acc[2][3] += a2 * bv.w;
            acc[3][0] += a3 * bv.x; acc[3][1] += a3 * bv.y; acc[3][2] += a3 * bv.z; acc[3][3] += a3 * bv.w;
        }
    }

    #pragma unroll
    for (int i = 0; i < 4; i++) {
        int o = to + i;
        float bias = b[o];
        size_t off = ((size_t)(o >> 3) * NTOK + n) * DK + (o & 7) * 64 + thw;
        float4 hi4, lo4;
        float y;
        y = acc[i][0] + bias; hi4.x = __uint_as_float(tf32_of(y)); lo4.x = __uint_as_float(tf32_of(y - hi4.x));
        y = acc[i][1] + bias; hi4.y = __uint_as_float(tf32_of(y)); lo4.y = __uint_as_float(tf32_of(y - hi4.y));
        y = acc[i][2] + bias; hi4.z = __uint_as_float(tf32_of(y)); lo4.z = __uint_as_float(tf32_of(y - hi4.z));
        y = acc[i][3] + bias; hi4.w = __uint_as_float(tf32_of(y)); lo4.w = __uint_as_float(tf32_of(y - hi4.w));
        *(float4*)(dhi + off) = hi4;
        *(float4*)(dlo + off) = lo4;
    }
}

// =====================================================================
// Kernel 2: S = (Q K^T)*alpha via 3xTF32 mma.sync
// block 128x128x(k32 stages), 128 threads, 4 warps of 64x64
// smem per buffer: Ah,Al,Bh,Bl each [128][32] floats, XOR swizzled
// =====================================================================
#define QK_BUF_FLOATS (4 * 128 * 32)          // 16384 floats
#define QK_SMEM (2 * QK_BUF_FLOATS * 4)       // 131072 bytes

__global__ __launch_bounds__(128) void qk_mma(
    const float* __restrict__ Qh, const float* __restrict__ Ql,
    const float* __restrict__ Kh, const float* __restrict__ Kl,
    float* __restrict__ C)
{
    extern __shared__ float sm[];
    const int t = threadIdx.x;
    const int lane = t & 31, wid = t >> 5;
    const int g = lane >> 2, tig = lane & 3;
    const int h = blockIdx.z;
    const int m0 = blockIdx.y * 128, n0 = blockIdx.x * 128;
    const long long hoff = (long long)h * NTOK * DK;

    const float* a_hi = Qh + hoff + (long long)m0 * DK;
    const float* a_lo = Ql + hoff + (long long)m0 * DK;
    const float* b_hi = Kh + hoff + (long long)n0 * DK;
    const float* b_lo = Kl + hoff + (long long)n0 * DK;

    const uint32_t smem_u32 = (uint32_t)__cvta_generic_to_shared(sm);

    auto issue = [&](int s) {
        const uint32_t sb = smem_u32 + (uint32_t)(s & 1) * QK_BUF_FLOATS * 4;
        const int k0 = s * 32;
        #pragma unroll
        for (int i = 0; i < 8; i++) {
            int idx = i * 128 + t;
            int row = idx >> 3, cw = idx & 7;
            uint32_t doff = (uint32_t)(row * 32 + ((cw ^ (row & 7)) * 4)) * 4;
            long long soff = (long long)row * DK + k0 + cw * 4;
            cpa16(sb + doff,                 a_hi + soff);
            cpa16(sb + 4096u * 4 + doff,     a_lo + soff);
            cpa16(sb + 8192u * 4 + doff,     b_hi + soff);
            cpa16(sb + 12288u * 4 + doff,    b_lo + soff);
        }
        cpa_commit();
    };

    float acc[4][8][4];
    #pragma unroll
    for (int mt = 0; mt < 4; mt++)
        #pragma unroll
        for (int nt = 0; nt < 8; nt++)
            #pragma unroll
            for (int r = 0; r < 4; r++) acc[mt][nt][r] = 0.0f;

    const int wm = (wid & 1) * 64;
    const int wn = (wid >> 1) * 64;

    issue(0);

    const int NS = DK / 32;  // 16
    for (int s = 0; s < NS; s++) {
        cpa_wait0();
        __syncthreads();
        if (s + 1 < NS) issue(s + 1);

        const float* sAh = sm + (s & 1) * QK_BUF_FLOATS;
        const float* sAl = sAh + 4096;
        const float* sBh = sAh + 8192;
        const float* sBl = sAh + 12288;

        #pragma unroll
        for (int kk8 = 0; kk8 < 4; kk8++) {
            const int kc = kk8 * 8;
            const int c0 = (kc + tig)     ^ (g * 4);
            const int c1 = (kc + tig + 4) ^ (g * 4);

            uint32_t Ah[4][4], Al[4][4];
            #pragma unroll
            for (int mt = 0; mt < 4; mt++) {
                int r0 = (wm + mt * 16 + g) * 32;
                int r1 = r0 + 8 * 32;
                Ah[mt][0] = fbits(sAh[r0 + c0]); Ah[mt][1] = fbits(sAh[r1 + c0]);
                Ah[mt][2] = fbits(sAh[r0 + c1]); Ah[mt][3] = fbits(sAh[r1 + c1]);
                Al[mt][0] = fbits(sAl[r0 + c0]); Al[mt][1] = fbits(sAl[r1 + c0]);
                Al[mt][2] = fbits(sAl[r0 + c1]); Al[mt][3] = fbits(sAl[r1 + c1]);
            }
            uint32_t Bh[8][2], Bl[8][2];
            #pragma unroll
            for (int nt = 0; nt < 8; nt++) {
                int nr = (wn + nt * 8 + g) * 32;
                Bh[nt][0] = fbits(sBh[nr + c0]); Bh[nt][1] = fbits(sBh[nr + c1]);
                Bl[nt][0] = fbits(sBl[nr + c0]); Bl[nt][1] = fbits(sBl[nr + c1]);
            }
            #pragma unroll
            for (int mt = 0; mt < 4; mt++)
                #pragma unroll
                for (int nt = 0; nt < 8; nt++) {
                    mma8(acc[mt][nt], Ah[mt], Bh[nt]);
                    mma8(acc[mt][nt], Ah[mt], Bl[nt]);
                    mma8(acc[mt][nt], Al[mt], Bh[nt]);
                }
        }
        __syncthreads();
    }

    float* Cb = C + (long long)h * NTOK * NTOK;
    #pragma unroll
    for (int mt = 0; mt < 4; mt++) {
        int row = m0 + wm + mt * 16 + g;
        #pragma unroll
        for (int nt = 0; nt < 8; nt++) {
            int col = n0 + wn + nt * 8 + 2 * tig;
            float2 v0 = make_float2(acc[mt][nt][0] * ATTN_SCALE, acc[mt][nt][1] * ATTN_SCALE);
            float2 v1 = make_float2(acc[mt][nt][2] * ATTN_SCALE, acc[mt][nt][3] * ATTN_SCALE);
            *(float2*)&Cb[(long long)row * NTOK + col]       = v0;
            *(float2*)&Cb[(long long)(row + 8) * NTOK + col] = v1;
        }
    }
}

// =====================================================================
// Kernel 4: O = P @ V via 3xTF32 (P split in-register, V pre-split)
// block 128x128x(k32), A=P fp32 staged swizzled; B=V[k][n] staged [32][136]
// =====================================================================
#define PV_A_FLOATS (128 * 32)                 // 4096
#define PV_B_FLOATS (32 * 136)                 // 4352
#define PV_BUF_FLOATS (PV_A_FLOATS + 2 * PV_B_FLOATS)   // 12800
#define PV_SMEM (2 * PV_BUF_FLOATS * 4)        // 102400 bytes

__global__ __launch_bounds__(128) void pv_mma(
    const float* __restrict__ P,
    const float* __restrict__ Vh, const float* __restrict__ Vl,
    float* __restrict__ O)
{
    extern __shared__ float sm[];
    const int t = threadIdx.x;
    const int lane = t & 31, wid = t >> 5;
    const int g = lane >> 2, tig = lane & 3;
    const int h = blockIdx.z;
    const int m0 = blockIdx.y * 128, n0 = blockIdx.x * 128;

    const float* Ab  = P  + (long long)h * NTOK * NTOK + (long long)m0 * NTOK;
    const float* Bhb = Vh + (long long)h * NTOK * DK + n0;
    const float* Blb = Vl + (long long)h * NTOK * DK + n0;

    const uint32_t smem_u32 = (uint32_t)__cvta_generic_to_shared(sm);

    auto issue = [&](int s) {
        const uint32_t sb = smem_u32 + (uint32_t)(s & 1) * PV_BUF_FLOATS * 4;
        const int k0 = s * 32;
        // A tile: [128][32] swizzled
        #pragma unroll
        for (int i = 0; i < 8; i++) {
            int idx = i * 128 + t;
            int row = idx >> 3, cw = idx & 7;
            uint32_t doff = (uint32_t)(row * 32 + ((cw ^ (row & 7)) * 4)) * 4;
            cpa16(sb + doff, Ab + (long long)row * NTOK + k0 + cw * 4);
        }
        // B tiles: [32][136]
        #pragma unroll
        for (int i = 0; i < 8; i++) {
            int idx = i * 128 + t;
            int k = idx >> 5, c4 = (idx & 31) * 4;
            uint32_t doff = (uint32_t)(k * 136 + c4) * 4;
            long long soff = (long long)(k0 + k) * DK + c4;
            cpa16(sb + PV_A_FLOATS * 4 + doff,                    Bhb + soff);
            cpa16(sb + (PV_A_FLOATS + PV_B_FLOATS) * 4 + doff,    Blb + soff);
        }
        cpa_commit();
    };

    float acc[4][8][4];
    #pragma unroll
    for (int mt = 0; mt < 4; mt++)
        #pragma unroll
        for (int nt = 0; nt < 8; nt++)
            #pragma unroll
            for (int r = 0; r < 4; r++) acc[mt][nt][r] = 0.0f;

    const int wm = (wid & 1) * 64;
    const int wn = (wid >> 1) * 64;

    issue(0);

    const int NS = NTOK / 32;  // 64
    for (int s = 0; s < NS; s++) {
        cpa_wait0();
        __syncthreads();
        if (s + 1 < NS) issue(s + 1);

        const float* sA  = sm + (s & 1) * PV_BUF_FLOATS;
        const float* sBh = sA + PV_A_FLOATS;
        const float* sBl = sBh + PV_B_FLOATS;

        #pragma unroll
        for (int kk8 = 0; kk8 < 4; kk8++) {
            const int kc = kk8 * 8;
            const int c0 = (kc + tig)     ^ (g * 4);
            const int c1 = (kc + tig + 4) ^ (g * 4);

            uint32_t Ah[4][4], Al[4][4];
            #pragma unroll
            for (int mt = 0; mt < 4; mt++) {
                int r0 = (wm + mt * 16 + g) * 32;
                int r1 = r0 + 8 * 32;
                float a;
                a = sA[r0 + c0]; Ah[mt][0] = tf32_of(a); Al[mt][0] = tf32_of(a - __uint_as_float(Ah[mt][0]));
                a = sA[r1 + c0]; Ah[mt][1] = tf32_of(a); Al[mt][1] = tf32_of(a - __uint_as_float(Ah[mt][1]));
                a = sA[r0 + c1]; Ah[mt][2] = tf32_of(a); Al[mt][2] = tf32_of(a - __uint_as_float(Ah[mt][2]));
                a = sA[r1 + c1]; Ah[mt][3] = tf32_of(a); Al[mt][3] = tf32_of(a - __uint_as_float(Ah[mt][3]));
            }
            uint32_t Bh[8][2], Bl[8][2];
            #pragma unroll
            for (int nt = 0; nt < 8; nt++) {
                int n = wn + nt * 8 + g;
                Bh[nt][0] = fbits(sBh[(kc + tig) * 136 + n]);
                Bh[nt][1] = fbits(sBh[(kc + tig + 4) * 136 + n]);
                Bl[nt][0] = fbits(sBl[(kc + tig) * 136 + n]);
                Bl[nt][1] = fbits(sBl[(kc + tig + 4) * 136 + n]);
            }
            #pragma unroll
            for (int mt = 0; mt < 4; mt++)
                #pragma unroll
                for (int nt = 0; nt < 8; nt++) {
                    mma8(acc[mt][nt], Ah[mt], Bh[nt]);
                    mma8(acc[mt][nt], Ah[mt], Bl[nt]);
                    mma8(acc[mt][nt], Al[mt], Bh[nt]);
                }
        }
        __syncthreads();
    }

    float* Ob = O + (long long)h * NTOK * DK;
    #pragma unroll
    for (int mt = 0; mt < 4; mt++) {
        int row = m0 + wm + mt * 16 + g;
        #pragma unroll
        for (int nt = 0; nt < 8; nt++) {
            int col = n0 + wn + nt * 8 + 2 * tig;
            *(float2*)&Ob[(long long)row * DK + col]       = make_float2(acc[mt][nt][0], acc[mt][nt][1]);
            *(float2*)&Ob[(long long)(row + 8) * DK + col] = make_float2(acc[mt][nt][2], acc[mt][nt][3]);
        }
    }
}

// =====================================================================
// Kernel 3: in-place row softmax over 2048 columns (one block per row)
// =====================================================================
__global__ __launch_bounds__(256) void softmax_rows(float* __restrict__ attn)
{
    float4* p4 = (float4*)(attn + (long long)blockIdx.x * NTOK);
    const int t = threadIdx.x;
    __shared__ float red[8];

    float4 v0 = p4[t];
    float4 v1 = p4[t + 256];

    float m = fmaxf(fmaxf(fmaxf(v0.x, v0.y), fmaxf(v0.z, v0.w)),
                    fmaxf(fmaxf(v1.x, v1.y), fmaxf(v1.z, v1.w)));
    #pragma unroll
    for (int o = 16; o; o >>= 1) m = fmaxf(m, __shfl_xor_sync(0xffffffffu, m, o));
    if ((t & 31) == 0) red[t >> 5] = m;
    __syncthreads();
    if (t < 32) {
        float r = (t < 8) ? red[t] : -3.4e38f;
        #pragma unroll
        for (int o = 4; o; o >>= 1) r = fmaxf(r, __shfl_xor_sync(0xffffffffu, r, o));
        if (t == 0) red[0] = r;
    }
    __syncthreads();
    m = red[0];
    __syncthreads();

    v0.x = __expf(v0.x - m); v0.y = __expf(v0.y - m);
    v0.z = __expf(v0.z - m); v0.w = __expf(v0.w - m);
    v1.x = __expf(v1.x - m); v1.y = __expf(v1.y - m);
    v1.z = __expf(v1.z - m); v1.w = __expf(v1.w - m);

    float s = v0.x + v0.y + v0.z + v0.w + v1.x + v1.y + v1.z + v1.w;
    #pragma unroll
    for (int o = 16; o; o >>= 1) s += __shfl_xor_sync(0xffffffffu, s, o);
    if ((t & 31) == 0) red[t >> 5] = s;
    __syncthreads();
    if (t < 32) {
        float r = (t < 8) ? red[t] : 0.0f;
        #pragma unroll
        for (int o = 4; o; o >>= 1) r += __shfl_xor_sync(0xffffffffu, r, o);
        if (t == 0) red[0] = r;
    }
    __syncthreads();
    float inv = 1.0f / red[0];

    v0.x *= inv; v0.y *= inv; v0.z *= inv; v0.w *= inv;
    v1.x *= inv; v1.y *= inv; v1.z *= inv; v1.w *= inv;
    p4[t] = v0;
    p4[t + 256] = v1;
}

// =====================================================================
// Kernel 5: fc + residual + InstanceNorm (scalar round-3 form)
// =====================================================================
#define K3_SMEM ((256 * 65 + 64 * 68 + 256 * 68) * 4)
__global__ __launch_bounds__(256) void fc_norm_kernel(
    const float* __restrict__ oatt, const float* __restrict__ Wfc,
    const float* __restrict__ bfc, const float* __restrict__ q,
    float* __restrict__ out)
{
    extern __shared__ float sm[];
    float* Wfs = sm;                 // 256 x 65
    float* att = Wfs + 256 * 65;     // 64 x 68
    float* ys  = att + 64 * 68;      // 256 x 68

    const int n = blockIdx.x;
    const int t = threadIdx.x;

    #pragma unroll 4
    for (int i = 0; i < 64; i++) {
        int e = i * 256 + t;
        Wfs[(e >> 6) * 65 + (e & 63)] = Wfc[e];
        ys[(e >> 6) * 68 + (e & 63)] = q[(size_t)n * 16384 + e];
    }
    #pragma unroll
    for (int i = 0; i < 16; i++) {
        int e = i * 256 + t;
        int oc = e >> 6, hw = e & 63;
        att[oc * 68 + hw] =
            oatt[((size_t)(oc >> 3) * NTOK + n) * DK + (oc & 7) * 64 + hw];
    }
    __syncthreads();

    const int c = t;
    float4 acc[16];
    #pragma unroll
    for (int j = 0; j < 16; j++) acc[j] = make_float4(0.f, 0.f, 0.f, 0.f);

    for (int oc = 0; oc < 64; oc++) {
        float w = Wfs[c * 65 + oc];
        const float4* arow = (const float4*)&att[oc * 68];
        #pragma unroll
        for (int j = 0; j < 16; j++) {
            float4 v = arow[j];
            acc[j].x += w * v.x; acc[j].y += w * v.y;
            acc[j].z += w * v.z; acc[j].w += w * v.w;
        }
    }

    float bias = bfc[c];
    float4* yrow = (float4*)&ys[c * 68];
    float s = 0.f, s2 = 0.f;
    #pragma unroll
    for (int j = 0; j < 16; j++) {
        float4 r = yrow[j];
        float4 a = acc[j];
        a.x += bias + r.x; a.y += bias + r.y;
        a.z += bias + r.z; a.w += bias + r.w;
        acc[j] = a;
        s  += a.x + a.y + a.z + a.w;
        s2 += a.x * a.x + a.y * a.y + a.z * a.z + a.w * a.w;
    }
    float mean = s * (1.0f / 64.0f);
    float var  = s2 * (1.0f / 64.0f) - mean * mean;
    float inv  = rsqrtf(var + 1e-5f);
    #pragma unroll
    for (int j = 0; j < 16; j++) {
        float4 a = acc[j];
        a.x = (a.x - mean) * inv; a.y = (a.y - mean) * inv;
        a.z = (a.z - mean) * inv; a.w = (a.w - mean) * inv;
        yrow[j] = a;
    }
    __syncthreads();
    #pragma unroll 4
    for (int i = 0; i < 64; i++) {
        int e = i * 256 + t;
        out[(size_t)n * 16384 + e] = ys[(e >> 6) * 68 + (e & 63)];
    }
}

// =====================================================================
extern "C" void kernel_launch(void* const* d_in, const int* in_sizes, int n_in,
                              void* d_out, int out_size)
{
    const float* q   = (const float*)d_in[0];
    const float* k   = (const float*)d_in[1];
    const float* v   = (const float*)d_in[2];
    const float* Wq  = (const float*)d_in[3];
    const float* bq  = (const float*)d_in[4];
    const float* Wk  = (const float*)d_in[5];
    const float* bk  = (const float*)d_in[6];
    const float* Wv  = (const float*)d_in[7];
    const float* bv  = (const float*)d_in[8];
    const float* Wfc = (const float*)d_in[9];
    const float* bfc = (const float*)d_in[10];
    float* out = (float*)d_out;

    float *p_qhi, *p_qlo, *p_khi, *p_klo, *p_vhi, *p_vlo, *p_o, *p_attn_scr;
    cudaGetSymbolAddress((void**)&p_qhi, g_qhi);
    cudaGetSymbolAddress((void**)&p_qlo, g_qlo);
    cudaGetSymbolAddress((void**)&p_khi, g_khi);
    cudaGetSymbolAddress((void**)&p_klo, g_klo);
    cudaGetSymbolAddress((void**)&p_vhi, g_vhi);
    cudaGetSymbolAddress((void**)&p_vlo, g_vlo);
    cudaGetSymbolAddress((void**)&p_o,   g_o);
    cudaGetSymbolAddress((void**)&p_attn_scr, g_attn_scratch);

    const size_t OUT_ELEMS  = (size_t)NTOK * CIN * HWSZ;          // 33554432
    const size_t ATTN_ELEMS = (size_t)NHEAD * NTOK * NTOK;        // 33554432
    float* attn = ((size_t)out_size >= OUT_ELEMS + ATTN_ELEMS)
                      ? out + OUT_ELEMS : p_attn_scr;

    // one-time attribute setup (host-side, capture-safe)
    cudaFuncSetAttribute(qk_mma, cudaFuncAttributeMaxDynamicSharedMemorySize, QK_SMEM);
    cudaFuncSetAttribute(pv_mma, cudaFuncAttributeMaxDynamicSharedMemorySize, PV_SMEM);
    cudaFuncSetAttribute(fc_norm_kernel, cudaFuncAttributeMaxDynamicSharedMemorySize, K3_SMEM);

    // 1) projections with tf32 hi/lo split
    proj_kernel<<<NTOK, 256>>>(q, Wq, bq, p_qhi, p_qlo);
    proj_kernel<<<NTOK, 256>>>(k, Wk, bk, p_khi, p_klo);
    proj_kernel<<<NTOK, 256>>>(v, Wv, bv, p_vhi, p_vlo);

    // 2) scores = (Q K^T)/sqrt(512)   [tensor cores, 3xTF32]
    {
        dim3 grid(NTOK / 128, NTOK / 128, NHEAD);
        qk_mma<<<grid, 128, QK_SMEM>>>(p_qhi, p_qlo, p_khi, p_klo, attn);
    }

    // 3) softmax over keys, in place
    softmax_rows<<<NHEAD * NTOK, 256>>>(attn);

    // 4) O = P @ V   [tensor cores, 3xTF32]
    {
        dim3 grid(DK / 128, NTOK / 128, NHEAD);
        pv_mma<<<grid, 128, PV_SMEM>>>(attn, p_vhi, p_vlo, p_o);
    }

    // 5) fc + residual + instance norm
    fc_norm_kernel<<<NTOK, 256, K3_SMEM>>>(p_o, Wfc, bfc, q, out);
}

// round 15
// speedup vs baseline: 1.1884x; 1.0295x over previous
#include <cuda_runtime.h>
#include <math.h>
#include <stdint.h>

#define NTOK 2048
#define NHEAD 8
#define DK 512
#define CIN 256
#define HWSZ 64
#define ATTN_SCALE 0.04419417382415922f  // 1/sqrt(512)

// ---------------- device scratch (no cudaMalloc allowed) ----------------
#define HTD ((size_t)NHEAD * NTOK * DK)
__device__ float g_qhi[HTD];
__device__ float g_qlo[HTD];
__device__ float g_khi[HTD];
__device__ float g_klo[HTD];
__device__ float g_vhi[HTD];
__device__ float g_vlo[HTD];
__device__ float g_o  [HTD];
__device__ float g_attn_scratch[(size_t)NHEAD * NTOK * NTOK];

// ---------------- small helpers ----------------
__device__ __forceinline__ uint32_t tf32_of(float x) {
    uint32_t r;
    asm("cvt.rna.tf32.f32 %0, %1;" : "=r"(r) : "f"(x));
    return r;
}
__device__ __forceinline__ void cpa16(uint32_t saddr, const void* gptr) {
    asm volatile("cp.async.ca.shared.global [%0], [%1], 16;"
                 :: "r"(saddr), "l"(gptr));
}
__device__ __forceinline__ void cpa_commit() {
    asm volatile("cp.async.commit_group;");
}
__device__ __forceinline__ void cpa_wait0() {
    asm volatile("cp.async.wait_group 0;");
}
__device__ __forceinline__ void mma8(float* d, const uint32_t* a, const uint32_t* b) {
    asm volatile(
        "mma.sync.aligned.m16n8k8.row.col.f32.tf32.tf32.f32 "
        "{%0,%1,%2,%3}, {%4,%5,%6,%7}, {%8,%9}, {%0,%1,%2,%3};"
        : "+f"(d[0]), "+f"(d[1]), "+f"(d[2]), "+f"(d[3])
        : "r"(a[0]), "r"(a[1]), "r"(a[2]), "r"(a[3]),
          "r"(b[0]), "r"(b[1]));
}
__device__ __forceinline__ uint32_t fbits(float x) { return __float_as_uint(x); }

// =====================================================================
// Kernel 1: projection (scalar fp32) + tf32 hi/lo split epilogue
// =====================================================================
__global__ __launch_bounds__(256) void proj_kernel(
    const float* __restrict__ x, const float* __restrict__ W,
    const float* __restrict__ b,
    float* __restrict__ dhi, float* __restrict__ dlo)
{
    __shared__ float Xs[64][68];
    __shared__ float Ws[64][68];
    const int n = blockIdx.x;
    const int t = threadIdx.x;
    const int to  = (t >> 4) * 4;
    const int thw = (t & 15) * 4;

    const float* xn = x + (size_t)n * CIN * HWSZ;
    float acc[4][4] = {};

    for (int cc = 0; cc < CIN; cc += 64) {
        __syncthreads();
        #pragma unroll
        for (int i = 0; i < 16; i++) {
            int e = i * 256 + t;
            Xs[e >> 6][e & 63] = xn[(size_t)cc * 64 + e];
            Ws[e >> 6][e & 63] = W[(size_t)(e >> 6) * CIN + cc + (e & 63)];
        }
        __syncthreads();
        #pragma unroll
        for (int c1 = 0; c1 < 64; c1++) {
            float a0 = Ws[to + 0][c1], a1 = Ws[to + 1][c1];
            float a2 = Ws[to + 2][c1], a3 = Ws[to + 3][c1];
            float4 bv = *(const float4*)&Xs[c1][thw];
            acc[0][0] += a0 * bv.x; acc[0][1] += a0 * bv.y; acc[0][2] += a0 * bv.z; acc[0][3] += a0 * bv.w;
            acc[1][0] += a1 * bv.x; acc[1][1] += a1 * bv.y; acc[1][2] += a1 * bv.z; acc[1][3] += a1 * bv.w;
            acc[2][0] += a2 * bv.x; acc[2][1] += a2 * bv.y; acc[2][2] += a2 * bv.z; acc[2][3] += a2 * bv.w;
            acc[3][0] += a3 * bv.x; acc[3][1] += a3 * bv.y; acc[3][2] += a3 * bv.z; acc[3][3] += a3 * bv.w;
        }
    }

    #pragma unroll
    for (int i = 0; i < 4; i++) {
        int o = to + i;
        float bias = b[o];
        size_t off = ((size_t)(o >> 3) * NTOK + n) * DK + (o & 7) * 64 + thw;
        float4 hi4, lo4;
        float y;
        y = acc[i][0] + bias; hi4.x = __uint_as_float(tf32_of(y)); lo4.x = __uint_as_float(tf32_of(y - hi4.x));
        y = acc[i][1] + bias; hi4.y = __uint_as_float(tf32_of(y)); lo4.y = __uint_as_float(tf32_of(y - hi4.y));
        y = acc[i][2] + bias; hi4.z = __uint_as_float(tf32_of(y)); lo4.z = __uint_as_float(tf32_of(y - hi4.z));
        y = acc[i][3] + bias; hi4.w = __uint_as_float(tf32_of(y)); lo4.w = __uint_as_float(tf32_of(y - hi4.w));
        *(float4*)(dhi + off) = hi4;
        *(float4*)(dlo + off) = lo4;
    }
}

// =====================================================================
// Kernel 2: S = (Q K^T)*alpha via 3xTF32 mma.sync
// 256 threads, 8 warps of 32x64 (low reg pressure, no spill)
// smem per buffer: Ah,Al,Bh,Bl each [128][32] floats, XOR swizzled
// =====================================================================
#define QK_BUF_FLOATS (4 * 128 * 32)          // 16384 floats
#define QK_SMEM (2 * QK_BUF_FLOATS * 4)       // 131072 bytes

__global__ __launch_bounds__(256) void qk_mma(
    const float* __restrict__ Qh, const float* __restrict__ Ql,
    const float* __restrict__ Kh, const float* __restrict__ Kl,
    float* __restrict__ C)
{
    extern __shared__ float sm[];
    const int t = threadIdx.x;
    const int lane = t & 31, wid = t >> 5;
    const int g = lane >> 2, tig = lane & 3;
    const int h = blockIdx.z;
    const int m0 = blockIdx.y * 128, n0 = blockIdx.x * 128;
    const long long hoff = (long long)h * NTOK * DK;

    const float* a_hi = Qh + hoff + (long long)m0 * DK;
    const float* a_lo = Ql + hoff + (long long)m0 * DK;
    const float* b_hi = Kh + hoff + (long long)n0 * DK;
    const float* b_lo = Kl + hoff + (long long)n0 * DK;

    const uint32_t smem_u32 = (uint32_t)__cvta_generic_to_shared(sm);

    auto issue = [&](int s) {
        const uint32_t sb = smem_u32 + (uint32_t)(s & 1) * QK_BUF_FLOATS * 4;
        const int k0 = s * 32;
        #pragma unroll
        for (int i = 0; i < 4; i++) {
            int idx = i * 256 + t;
            int row = idx >> 3, cw = idx & 7;
            uint32_t doff = (uint32_t)(row * 32 + ((cw ^ (row & 7)) * 4)) * 4;
            long long soff = (long long)row * DK + k0 + cw * 4;
            cpa16(sb + doff,                 a_hi + soff);
            cpa16(sb + 4096u * 4 + doff,     a_lo + soff);
            cpa16(sb + 8192u * 4 + doff,     b_hi + soff);
            cpa16(sb + 12288u * 4 + doff,    b_lo + soff);
        }
        cpa_commit();
    };

    float acc[2][8][4];
    #pragma unroll
    for (int mt = 0; mt < 2; mt++)
        #pragma unroll
        for (int nt = 0; nt < 8; nt++)
            #pragma unroll
            for (int r = 0; r < 4; r++) acc[mt][nt][r] = 0.0f;

    const int wm = (wid & 3) * 32;   // 4 M-groups of 32
    const int wn = (wid >> 2) * 64;  // 2 N-groups of 64

    issue(0);

    const int NS = DK / 32;  // 16
    for (int s = 0; s < NS; s++) {
        cpa_wait0();
        __syncthreads();
        if (s + 1 < NS) issue(s + 1);

        const float* sAh = sm + (s & 1) * QK_BUF_FLOATS;
        const float* sAl = sAh + 4096;
        const float* sBh = sAh + 8192;
        const float* sBl = sAh + 12288;

        #pragma unroll
        for (int kk8 = 0; kk8 < 4; kk8++) {
            const int kc = kk8 * 8;
            const int c0 = (kc + tig)     ^ (g * 4);
            const int c1 = (kc + tig + 4) ^ (g * 4);

            uint32_t Ah[2][4], Al[2][4];
            #pragma unroll
            for (int mt = 0; mt < 2; mt++) {
                int r0 = (wm + mt * 16 + g) * 32;
                int r1 = r0 + 8 * 32;
                Ah[mt][0] = fbits(sAh[r0 + c0]); Ah[mt][1] = fbits(sAh[r1 + c0]);
                Ah[mt][2] = fbits(sAh[r0 + c1]); Ah[mt][3] = fbits(sAh[r1 + c1]);
                Al[mt][0] = fbits(sAl[r0 + c0]); Al[mt][1] = fbits(sAl[r1 + c0]);
                Al[mt][2] = fbits(sAl[r0 + c1]); Al[mt][3] = fbits(sAl[r1 + c1]);
            }
            uint32_t Bh[8][2], Bl[8][2];
            #pragma unroll
            for (int nt = 0; nt < 8; nt++) {
                int nr = (wn + nt * 8 + g) * 32;
                Bh[nt][0] = fbits(sBh[nr + c0]); Bh[nt][1] = fbits(sBh[nr + c1]);
                Bl[nt][0] = fbits(sBl[nr + c0]); Bl[nt][1] = fbits(sBl[nr + c1]);
            }
            #pragma unroll
            for (int mt = 0; mt < 2; mt++)
                #pragma unroll
                for (int nt = 0; nt < 8; nt++) {
                    mma8(acc[mt][nt], Ah[mt], Bh[nt]);
                    mma8(acc[mt][nt], Ah[mt], Bl[nt]);
                    mma8(acc[mt][nt], Al[mt], Bh[nt]);
                }
        }
        __syncthreads();
    }

    float* Cb = C + (long long)h * NTOK * NTOK;
    #pragma unroll
    for (int mt = 0; mt < 2; mt++) {
        int row = m0 + wm + mt * 16 + g;
        #pragma unroll
        for (int nt = 0; nt < 8; nt++) {
            int col = n0 + wn + nt * 8 + 2 * tig;
            float2 v0 = make_float2(acc[mt][nt][0] * ATTN_SCALE, acc[mt][nt][1] * ATTN_SCALE);
            float2 v1 = make_float2(acc[mt][nt][2] * ATTN_SCALE, acc[mt][nt][3] * ATTN_SCALE);
            *(float2*)&Cb[(long long)row * NTOK + col]       = v0;
            *(float2*)&Cb[(long long)(row + 8) * NTOK + col] = v1;
        }
    }
}

// =====================================================================
// Kernel 4: O = P @ V via 3xTF32 (P split in-register, V pre-split)
// 256 threads, 8 warps of 32x64
// =====================================================================
#define PV_A_FLOATS (128 * 32)                 // 4096
#define PV_B_FLOATS (32 * 136)                 // 4352
#define PV_BUF_FLOATS (PV_A_FLOATS + 2 * PV_B_FLOATS)   // 12800
#define PV_SMEM (2 * PV_BUF_FLOATS * 4)        // 102400 bytes

__global__ __launch_bounds__(256) void pv_mma(
    const float* __restrict__ P,
    const float* __restrict__ Vh, const float* __restrict__ Vl,
    float* __restrict__ O)
{
    extern __shared__ float sm[];
    const int t = threadIdx.x;
    const int lane = t & 31, wid = t >> 5;
    const int g = lane >> 2, tig = lane & 3;
    const int h = blockIdx.z;
    const int m0 = blockIdx.y * 128, n0 = blockIdx.x * 128;

    const float* Ab  = P  + (long long)h * NTOK * NTOK + (long long)m0 * NTOK;
    const float* Bhb = Vh + (long long)h * NTOK * DK + n0;
    const float* Blb = Vl + (long long)h * NTOK * DK + n0;

    const uint32_t smem_u32 = (uint32_t)__cvta_generic_to_shared(sm);

    auto issue = [&](int s) {
        const uint32_t sb = smem_u32 + (uint32_t)(s & 1) * PV_BUF_FLOATS * 4;
        const int k0 = s * 32;
        // A tile: [128][32] swizzled (1024 chunks, 4 per thread)
        #pragma unroll
        for (int i = 0; i < 4; i++) {
            int idx = i * 256 + t;
            int row = idx >> 3, cw = idx & 7;
            uint32_t doff = (uint32_t)(row * 32 + ((cw ^ (row & 7)) * 4)) * 4;
            cpa16(sb + doff, Ab + (long long)row * NTOK + k0 + cw * 4);
        }
        // B tiles: [32][136] (1024 chunks each, 4 per thread)
        #pragma unroll
        for (int i = 0; i < 4; i++) {
            int idx = i * 256 + t;
            int k = idx >> 5, c4 = (idx & 31) * 4;
            uint32_t doff = (uint32_t)(k * 136 + c4) * 4;
            long long soff = (long long)(k0 + k) * DK + c4;
            cpa16(sb + PV_A_FLOATS * 4 + doff,                    Bhb + soff);
            cpa16(sb + (PV_A_FLOATS + PV_B_FLOATS) * 4 + doff,    Blb + soff);
        }
        cpa_commit();
    };

    float acc[2][8][4];
    #pragma unroll
    for (int mt = 0; mt < 2; mt++)
        #pragma unroll
        for (int nt = 0; nt < 8; nt++)
            #pragma unroll
            for (int r = 0; r < 4; r++) acc[mt][nt][r] = 0.0f;

    const int wm = (wid & 3) * 32;
    const int wn = (wid >> 2) * 64;

    issue(0);

    const int NS = NTOK / 32;  // 64
    for (int s = 0; s < NS; s++) {
        cpa_wait0();
        __syncthreads();
        if (s + 1 < NS) issue(s + 1);

        const float* sA  = sm + (s & 1) * PV_BUF_FLOATS;
        const float* sBh = sA + PV_A_FLOATS;
        const float* sBl = sBh + PV_B_FLOATS;

        #pragma unroll
        for (int kk8 = 0; kk8 < 4; kk8++) {
            const int kc = kk8 * 8;
            const int c0 = (kc + tig)     ^ (g * 4);
            const int c1 = (kc + tig + 4) ^ (g * 4);

            uint32_t Ah[2][4], Al[2][4];
            #pragma unroll
            for (int mt = 0; mt < 2; mt++) {
                int r0 = (wm + mt * 16 + g) * 32;
                int r1 = r0 + 8 * 32;
                float a;
                a = sA[r0 + c0]; Ah[mt][0] = tf32_of(a); Al[mt][0] = tf32_of(a - __uint_as_float(Ah[mt][0]));
                a = sA[r1 + c0]; Ah[mt][1] = tf32_of(a); Al[mt][1] = tf32_of(a - __uint_as_float(Ah[mt][1]));
                a = sA[r0 + c1]; Ah[mt][2] = tf32_of(a); Al[mt][2] = tf32_of(a - __uint_as_float(Ah[mt][2]));
                a = sA[r1 + c1]; Ah[mt][3] = tf32_of(a); Al[mt][3] = tf32_of(a - __uint_as_float(Ah[mt][3]));
            }
            uint32_t Bh[8][2], Bl[8][2];
            #pragma unroll
            for (int nt = 0; nt < 8; nt++) {
                int n = wn + nt * 8 + g;
                Bh[nt][0] = fbits(sBh[(kc + tig) * 136 + n]);
                Bh[nt][1] = fbits(sBh[(kc + tig + 4) * 136 + n]);
                Bl[nt][0] = fbits(sBl[(kc + tig) * 136 + n]);
                Bl[nt][1] = fbits(sBl[(kc + tig + 4) * 136 + n]);
            }
            #pragma unroll
            for (int mt = 0; mt < 2; mt++)
                #pragma unroll
                for (int nt = 0; nt < 8; nt++) {
                    mma8(acc[mt][nt], Ah[mt], Bh[nt]);
                    mma8(acc[mt][nt], Ah[mt], Bl[nt]);
                    mma8(acc[mt][nt], Al[mt], Bh[nt]);
                }
        }
        __syncthreads();
    }

    float* Ob = O + (long long)h * NTOK * DK;
    #pragma unroll
    for (int mt = 0; mt < 2; mt++) {
        int row = m0 + wm + mt * 16 + g;
        #pragma unroll
        for (int nt = 0; nt < 8; nt++) {
            int col = n0 + wn + nt * 8 + 2 * tig;
            *(float2*)&Ob[(long long)row * DK + col]       = make_float2(acc[mt][nt][0], acc[mt][nt][1]);
            *(float2*)&Ob[(long long)(row + 8) * DK + col] = make_float2(acc[mt][nt][2], acc[mt][nt][3]);
        }
    }
}

// =====================================================================
// Kernel 3: in-place row softmax over 2048 columns (one block per row)
// =====================================================================
__global__ __launch_bounds__(256) void softmax_rows(float* __restrict__ attn)
{
    float4* p4 = (float4*)(attn + (long long)blockIdx.x * NTOK);
    const int t = threadIdx.x;
    __shared__ float red[8];

    float4 v0 = p4[t];
    float4 v1 = p4[t + 256];

    float m = fmaxf(fmaxf(fmaxf(v0.x, v0.y), fmaxf(v0.z, v0.w)),
                    fmaxf(fmaxf(v1.x, v1.y), fmaxf(v1.z, v1.w)));
    #pragma unroll
    for (int o = 16; o; o >>= 1) m = fmaxf(m, __shfl_xor_sync(0xffffffffu, m, o));
    if ((t & 31) == 0) red[t >> 5] = m;
    __syncthreads();
    if (t < 32) {
        float r = (t < 8) ? red[t] : -3.4e38f;
        #pragma unroll
        for (int o = 4; o; o >>= 1) r = fmaxf(r, __shfl_xor_sync(0xffffffffu, r, o));
        if (t == 0) red[0] = r;
    }
    __syncthreads();
    m = red[0];
    __syncthreads();

    v0.x = __expf(v0.x - m); v0.y = __expf(v0.y - m);
    v0.z = __expf(v0.z - m); v0.w = __expf(v0.w - m);
    v1.x = __expf(v1.x - m); v1.y = __expf(v1.y - m);
    v1.z = __expf(v1.z - m); v1.w = __expf(v1.w - m);

    float s = v0.x + v0.y + v0.z + v0.w + v1.x + v1.y + v1.z + v1.w;
    #pragma unroll
    for (int o = 16; o; o >>= 1) s += __shfl_xor_sync(0xffffffffu, s, o);
    if ((t & 31) == 0) red[t >> 5] = s;
    __syncthreads();
    if (t < 32) {
        float r = (t < 8) ? red[t] : 0.0f;
        #pragma unroll
        for (int o = 4; o; o >>= 1) r += __shfl_xor_sync(0xffffffffu, r, o);
        if (t == 0) red[0] = r;
    }
    __syncthreads();
    float inv = 1.0f / red[0];

    v0.x *= inv; v0.y *= inv; v0.z *= inv; v0.w *= inv;
    v1.x *= inv; v1.y *= inv; v1.z *= inv; v1.w *= inv;
    p4[t] = v0;
    p4[t + 256] = v1;
}

// =====================================================================
// Kernel 5: fc + residual + InstanceNorm
// =====================================================================
#define K3_SMEM ((256 * 65 + 64 * 68 + 256 * 68) * 4)
__global__ __launch_bounds__(256) void fc_norm_kernel(
    const float* __restrict__ oatt, const float* __restrict__ Wfc,
    const float* __restrict__ bfc, const float* __restrict__ q,
    float* __restrict__ out)
{
    extern __shared__ float sm[];
    float* Wfs = sm;                 // 256 x 65
    float* att = Wfs + 256 * 65;     // 64 x 68
    float* ys  = att + 64 * 68;      // 256 x 68

    const int n = blockIdx.x;
    const int t = threadIdx.x;

    #pragma unroll 4
    for (int i = 0; i < 64; i++) {
        int e = i * 256 + t;
        Wfs[(e >> 6) * 65 + (e & 63)] = Wfc[e];
        ys[(e >> 6) * 68 + (e & 63)] = q[(size_t)n * 16384 + e];
    }
    #pragma unroll
    for (int i = 0; i < 16; i++) {
        int e = i * 256 + t;
        int oc = e >> 6, hw = e & 63;
        att[oc * 68 + hw] =
            oatt[((size_t)(oc >> 3) * NTOK + n) * DK + (oc & 7) * 64 + hw];
    }
    __syncthreads();

    const int c = t;
    float4 acc[16];
    #pragma unroll
    for (int j = 0; j < 16; j++) acc[j] = make_float4(0.f, 0.f, 0.f, 0.f);

    for (int oc = 0; oc < 64; oc++) {
        float w = Wfs[c * 65 + oc];
        const float4* arow = (const float4*)&att[oc * 68];
        #pragma unroll
        for (int j = 0; j < 16; j++) {
            float4 v = arow[j];
            acc[j].x += w * v.x; acc[j].y += w * v.y;
            acc[j].z += w * v.z; acc[j].w += w * v.w;
        }
    }

    float bias = bfc[c];
    float4* yrow = (float4*)&ys[c * 68];
    float s = 0.f, s2 = 0.f;
    #pragma unroll
    for (int j = 0; j < 16; j++) {
        float4 r = yrow[j];
        float4 a = acc[j];
        a.x += bias + r.x; a.y += bias + r.y;
        a.z += bias + r.z; a.w += bias + r.w;
        acc[j] = a;
        s  += a.x + a.y + a.z + a.w;
        s2 += a.x * a.x + a.y * a.y + a.z * a.z + a.w * a.w;
    }
    float mean = s * (1.0f / 64.0f);
    float var  = s2 * (1.0f / 64.0f) - mean * mean;
    float inv  = rsqrtf(var + 1e-5f);
    #pragma unroll
    for (int j = 0; j < 16; j++) {
        float4 a = acc[j];
        a.x = (a.x - mean) * inv; a.y = (a.y - mean) * inv;
        a.z = (a.z - mean) * inv; a.w = (a.w - mean) * inv;
        yrow[j] = a;
    }
    __syncthreads();
    #pragma unroll 4
    for (int i = 0; i < 64; i++) {
        int e = i * 256 + t;
        out[(size_t)n * 16384 + e] = ys[(e >> 6) * 68 + (e & 63)];
    }
}

// =====================================================================
extern "C" void kernel_launch(void* const* d_in, const int* in_sizes, int n_in,
                              void* d_out, int out_size)
{
    const float* q   = (const float*)d_in[0];
    const float* k   = (const float*)d_in[1];
    const float* v   = (const float*)d_in[2];
    const float* Wq  = (const float*)d_in[3];
    const float* bq  = (const float*)d_in[4];
    const float* Wk  = (const float*)d_in[5];
    const float* bk  = (const float*)d_in[6];
    const float* Wv  = (const float*)d_in[7];
    const float* bv  = (const float*)d_in[8];
    const float* Wfc = (const float*)d_in[9];
    const float* bfc = (const float*)d_in[10];
    float* out = (float*)d_out;

    float *p_qhi, *p_qlo, *p_khi, *p_klo, *p_vhi, *p_vlo, *p_o, *p_attn_scr;
    cudaGetSymbolAddress((void**)&p_qhi, g_qhi);
    cudaGetSymbolAddress((void**)&p_qlo, g_qlo);
    cudaGetSymbolAddress((void**)&p_khi, g_khi);
    cudaGetSymbolAddress((void**)&p_klo, g_klo);
    cudaGetSymbolAddress((void**)&p_vhi, g_vhi);
    cudaGetSymbolAddress((void**)&p_vlo, g_vlo);
    cudaGetSymbolAddress((void**)&p_o,   g_o);
    cudaGetSymbolAddress((void**)&p_attn_scr, g_attn_scratch);

    const size_t OUT_ELEMS  = (size_t)NTOK * CIN * HWSZ;          // 33554432
    const size_t ATTN_ELEMS = (size_t)NHEAD * NTOK * NTOK;        // 33554432
    float* attn = ((size_t)out_size >= OUT_ELEMS + ATTN_ELEMS)
                      ? out + OUT_ELEMS : p_attn_scr;

    cudaFuncSetAttribute(qk_mma, cudaFuncAttributeMaxDynamicSharedMemorySize, QK_SMEM);
    cudaFuncSetAttribute(pv_mma, cudaFuncAttributeMaxDynamicSharedMemorySize, PV_SMEM);
    cudaFuncSetAttribute(fc_norm_kernel, cudaFuncAttributeMaxDynamicSharedMemorySize, K3_SMEM);

    // 1) projections with tf32 hi/lo split
    proj_kernel<<<NTOK, 256>>>(q, Wq, bq, p_qhi, p_qlo);
    proj_kernel<<<NTOK, 256>>>(k, Wk, bk, p_khi, p_klo);
    proj_kernel<<<NTOK, 256>>>(v, Wv, bv, p_vhi, p_vlo);

    // 2) scores = (Q K^T)/sqrt(512)   [tensor cores, 3xTF32]
    {
        dim3 grid(NTOK / 128, NTOK / 128, NHEAD);
        qk_mma<<<grid, 256, QK_SMEM>>>(p_qhi, p_qlo, p_khi, p_klo, attn);
    }

    // 3) softmax over keys, in place
    softmax_rows<<<NHEAD * NTOK, 256>>>(attn);

    // 4) O = P @ V   [tensor cores, 3xTF32]
    {
        dim3 grid(DK / 128, NTOK / 128, NHEAD);
        pv_mma<<<grid, 256, PV_SMEM>>>(attn, p_vhi, p_vlo, p_o);
    }

    // 5) fc + residual + instance norm
    fc_norm_kernel<<<NTOK, 256, K3_SMEM>>>(p_o, Wfc, bfc, q, out);
}